// round 17
// baseline (speedup 1.0000x reference)
#include <cuda_runtime.h>
#include <cuda_bf16.h>
#include <cstdint>

// HardNetLoss, screen-then-fix v8 (resubmit; R14 was an infra failure):
//   int8 screening GEMM -> per-8-element group maxes (no S~ dump),
//   scan: TWO-PASS group-max screen (no live 32-reg array, L1-hit reload),
//   lane-parallel exact fp32 dots via bounded drain-at-32 list, diag fused.

#define CNT 8192
#define KDIM 256
#define EPSV 1e-6f
#define MARGIN_C 0.04f

#define TSTRIDE 272
#define TILE_BYTES (128 * TSTRIDE)        // 34816
#define SM_TOTAL (2 * TILE_BYTES + 1024)  // 70656

__device__ unsigned char g_q[2 * CNT * KDIM];
__device__ __nv_bfloat16 g_grow[(size_t)CNT * 1024];   // row-dir group maxes (16MB)
__device__ __nv_bfloat16 g_gcol[(size_t)CNT * 1024];   // col-dir group maxes (16MB)
__device__ float g_erow[CNT], g_ecol[CNT];
__device__ float g_diag[CNT];
__device__ float g_partial[CNT / 256];
__device__ unsigned g_maxabs;

__device__ __forceinline__ uint32_t smem_u32(const void* p) {
    uint32_t a;
    asm("{ .reg .u64 t; cvta.to.shared.u64 t, %1; cvt.u32.u64 %0, t; }" : "=r"(a) : "l"(p));
    return a;
}
__device__ __forceinline__ void cp_async16(uint32_t saddr, const void* gaddr) {
    asm volatile("cp.async.cg.shared.global [%0], [%1], 16;" :: "r"(saddr), "l"(gaddr) : "memory");
}
__device__ __forceinline__ void mma_s8(int* c, const uint32_t* a, const uint32_t* b) {
    asm volatile(
        "mma.sync.aligned.m16n8k32.row.col.s32.s8.s8.s32 "
        "{%0,%1,%2,%3}, {%4,%5,%6,%7}, {%8,%9}, {%0,%1,%2,%3};"
        : "+r"(c[0]), "+r"(c[1]), "+r"(c[2]), "+r"(c[3])
        : "r"(a[0]), "r"(a[1]), "r"(a[2]), "r"(a[3]), "r"(b[0]), "r"(b[1]));
}
__device__ __forceinline__ float qscale() {
    return 126.5f / __uint_as_float(g_maxabs);
}

// warp-collective exact dot (diagonal only)
__device__ __forceinline__ float exact_dot(const float* __restrict__ x,
                                           int ar, int pr, int lane) {
    const float4* ap = reinterpret_cast<const float4*>(x + (size_t)ar * KDIM);
    const float4* pp = reinterpret_cast<const float4*>(x + (size_t)(CNT + pr) * KDIM);
    float sum = 0.0f;
#pragma unroll
    for (int t = 0; t < 2; t++) {
        float4 a = ap[lane * 2 + t], p = pp[lane * 2 + t];
        sum += a.x * p.x + a.y * p.y + a.z * p.z + a.w * p.w;
    }
#pragma unroll
    for (int st = 16; st; st >>= 1) sum += __shfl_xor_sync(~0u, sum, st);
    return sum;
}

// thread-local exact dot (one candidate per lane), bounded register footprint
__device__ __forceinline__ float thread_dot(const float* __restrict__ x,
                                            int ar, int pr) {
    const float4* ap = reinterpret_cast<const float4*>(x + (size_t)ar * KDIM);
    const float4* pp = reinterpret_cast<const float4*>(x + (size_t)(CNT + pr) * KDIM);
    float s0 = 0.0f, s1 = 0.0f;
#pragma unroll 4
    for (int i = 0; i < 64; i += 2) {
        float4 a = ap[i], p = pp[i];
        s0 += a.x * p.x + a.y * p.y + a.z * p.z + a.w * p.w;
        float4 a2 = ap[i + 1], p2 = pp[i + 1];
        s1 += a2.x * p2.x + a2.y * p2.y + a2.z * p2.z + a2.w * p2.w;
    }
    return s0 + s1;
}

// ---------------- prep ----------------
__global__ void maxabs_kernel(const float* __restrict__ x) {
    __shared__ float red[8];
    const float4* X4 = reinterpret_cast<const float4*>(x);
    int i = blockIdx.x * 256 + threadIdx.x;
    float m = 0.0f;
#pragma unroll
    for (int t = 0; t < 4; t++) {
        float4 v = X4[i + t * 262144];
        m = fmaxf(m, fmaxf(fmaxf(fabsf(v.x), fabsf(v.y)), fmaxf(fabsf(v.z), fabsf(v.w))));
    }
#pragma unroll
    for (int st = 16; st; st >>= 1) m = fmaxf(m, __shfl_xor_sync(~0u, m, st));
    if ((threadIdx.x & 31) == 0) red[threadIdx.x >> 5] = m;
    __syncthreads();
    if (threadIdx.x < 8) {
        m = red[threadIdx.x];
#pragma unroll
        for (int st = 4; st; st >>= 1) m = fmaxf(m, __shfl_xor_sync(0xffu, m, st));
        if (threadIdx.x == 0) atomicMax(&g_maxabs, __float_as_uint(m));
    }
}

__global__ void quant_kernel(const float* __restrict__ x) {
    int i = blockIdx.x * 256 + threadIdx.x;
    float sc = qscale();
    float4 v = reinterpret_cast<const float4*>(x)[i];
    float q[4] = {v.x, v.y, v.z, v.w};
    uint32_t w = 0;
#pragma unroll
    for (int j = 0; j < 4; j++)
        w |= ((uint32_t)((int)rintf(q[j] * sc) & 0xff)) << (8 * j);
    reinterpret_cast<uint32_t*>(g_q)[i] = w;
}

// ---------------- screening GEMM (unchanged from v6/v7) ----------------
__global__ __launch_bounds__(256, 2)
void gemm_screen() {
    extern __shared__ char smem[];
    const uint32_t sb = smem_u32(smem);
    const int tid = threadIdx.x;
    const int w = tid >> 5, l = tid & 31;
    const int wm = w >> 2, wn = w & 3;
    const int bx = blockIdx.x, by = blockIdx.y;

    const char* Ag = (const char*)g_q + (size_t)(by * 128) * KDIM;
    const char* Bg = (const char*)g_q + (size_t)(CNT + bx * 128) * KDIM;

#pragma unroll
    for (int i = 0; i < 8; i++) {
        int idx = tid + i * 256;
        int row = idx >> 4, c16 = idx & 15;
        uint32_t so = (uint32_t)row * TSTRIDE + c16 * 16;
        cp_async16(sb + so, Ag + row * KDIM + c16 * 16);
        cp_async16(sb + TILE_BYTES + so, Bg + row * KDIM + c16 * 16);
    }
    asm volatile("cp.async.commit_group;" ::: "memory");
    asm volatile("cp.async.wait_group 0;" ::: "memory");
    __syncthreads();

    int acc[16][4];
#pragma unroll
    for (int t = 0; t < 16; t++)
#pragma unroll
        for (int e = 0; e < 4; e++) acc[t][e] = 0;

#pragma unroll
    for (int k0 = 0; k0 < KDIM; k0 += 32) {
        uint32_t a[4][4], b[4][2];
#pragma unroll
        for (int mt = 0; mt < 4; mt++) {
            const char* p = smem + (uint32_t)(wm * 64 + mt * 16 + (l >> 2)) * TSTRIDE
                          + k0 + (l & 3) * 4;
            a[mt][0] = *reinterpret_cast<const uint32_t*>(p);
            a[mt][1] = *reinterpret_cast<const uint32_t*>(p + 8 * TSTRIDE);
            a[mt][2] = *reinterpret_cast<const uint32_t*>(p + 16);
            a[mt][3] = *reinterpret_cast<const uint32_t*>(p + 8 * TSTRIDE + 16);
        }
#pragma unroll
        for (int nt = 0; nt < 4; nt++) {
            const char* p = smem + TILE_BYTES + (uint32_t)(wn * 32 + nt * 8 + (l >> 2)) * TSTRIDE
                          + k0 + (l & 3) * 4;
            b[nt][0] = *reinterpret_cast<const uint32_t*>(p);
            b[nt][1] = *reinterpret_cast<const uint32_t*>(p + 16);
        }
#pragma unroll
        for (int mt = 0; mt < 4; mt++)
#pragma unroll
            for (int nt = 0; nt < 4; nt++)
                mma_s8(acc[mt * 4 + nt], a[mt], b[nt]);
    }

    // ---- epilogue: group maxes (diag-excluded), staged in smem, coalesced dump ----
    const float inv2 = 1.0f / (qscale() * qscale());
    __syncthreads();
    __nv_bfloat16* G1 = reinterpret_cast<__nv_bfloat16*>(smem);
    __nv_bfloat16* G2 = reinterpret_cast<__nv_bfloat16*>(smem + 4096);

#pragma unroll
    for (int mt = 0; mt < 4; mt++)
#pragma unroll
        for (int nt = 0; nt < 4; nt++)
#pragma unroll
            for (int h = 0; h < 2; h++) {
                int lr = wm * 64 + mt * 16 + (l >> 2) + h * 8;
                int lc = wn * 32 + nt * 8 + 2 * (l & 3);
                float s0 = (float)acc[mt * 4 + nt][2 * h + 0] * inv2;
                float s1 = (float)acc[mt * 4 + nt][2 * h + 1] * inv2;
                if (by * 128 + lr == bx * 128 + lc)     s0 = -2.0f;
                if (by * 128 + lr == bx * 128 + lc + 1) s1 = -2.0f;
                float g = fmaxf(s0, s1);
                g = fmaxf(g, __shfl_xor_sync(0xffffffffu, g, 1));
                g = fmaxf(g, __shfl_xor_sync(0xffffffffu, g, 2));
                if ((l & 3) == 0) G1[lr * 16 + wn * 4 + nt] = __float2bfloat16_rn(g);
                float c0 = s0, c1 = s1;
                c0 = fmaxf(c0, __shfl_xor_sync(0xffffffffu, c0, 4));
                c0 = fmaxf(c0, __shfl_xor_sync(0xffffffffu, c0, 8));
                c0 = fmaxf(c0, __shfl_xor_sync(0xffffffffu, c0, 16));
                c1 = fmaxf(c1, __shfl_xor_sync(0xffffffffu, c1, 4));
                c1 = fmaxf(c1, __shfl_xor_sync(0xffffffffu, c1, 8));
                c1 = fmaxf(c1, __shfl_xor_sync(0xffffffffu, c1, 16));
                if (l < 4) {
                    int gidx = wm * 8 + mt * 2 + h;
                    G2[(wn * 32 + nt * 8 + 2 * l) * 16 + gidx]     = __float2bfloat16_rn(c0);
                    G2[(wn * 32 + nt * 8 + 2 * l + 1) * 16 + gidx] = __float2bfloat16_rn(c1);
                }
            }
    __syncthreads();

    {
        int row = tid >> 1, half = tid & 1;
        uint4 v = *reinterpret_cast<const uint4*>(smem + row * 32 + half * 16);
        *reinterpret_cast<uint4*>(reinterpret_cast<char*>(g_grow)
            + ((size_t)(by * 128 + row) * 1024 + bx * 16 + half * 8) * 2) = v;
        uint4 w2 = *reinterpret_cast<const uint4*>(smem + 4096 + row * 32 + half * 16);
        *reinterpret_cast<uint4*>(reinterpret_cast<char*>(g_gcol)
            + ((size_t)(bx * 128 + row) * 1024 + by * 16 + half * 8) * 2) = w2;
    }
}

// ---------------- two-pass group-max scan + lane-parallel exact fix ----------------
__global__ __launch_bounds__(256, 6)
void scan6(const float* __restrict__ x) {
    __shared__ int lst[8][40];
    const int warp = threadIdx.x >> 5, lane = threadIdx.x & 31;
    const int r = blockIdx.x * 8 + warp;       // row (dir 0) or col (dir 1)
    const int dir = blockIdx.y;

    const char* base = reinterpret_cast<const char*>(
        (dir ? g_gcol : g_grow) + (size_t)r * 1024);

    // ---- pass 1: max only, nothing kept live ----
    float lmax = -2.0f;
#pragma unroll
    for (int c = 0; c < 4; c++) {
        uint4 ch = *reinterpret_cast<const uint4*>(base + c * 512 + lane * 16);
        __nv_bfloat162 p0 = *reinterpret_cast<__nv_bfloat162*>(&ch.x);
        __nv_bfloat162 p1 = *reinterpret_cast<__nv_bfloat162*>(&ch.y);
        __nv_bfloat162 p2 = *reinterpret_cast<__nv_bfloat162*>(&ch.z);
        __nv_bfloat162 p3 = *reinterpret_cast<__nv_bfloat162*>(&ch.w);
        __nv_bfloat162 mm = __hmax2(__hmax2(p0, p1), __hmax2(p2, p3));
        lmax = fmaxf(lmax, fmaxf(__low2float(mm), __high2float(mm)));
    }
#pragma unroll
    for (int st = 16; st; st >>= 1) lmax = fmaxf(lmax, __shfl_xor_sync(~0u, lmax, st));
    const float thr = lmax - MARGIN_C;

    float best = -2.0f;
    int cnt = 0;   // warp-uniform

    auto drain = [&](int n) {
        __syncwarp();
        int j = (lane < n) ? lst[warp][lane] : -1;
        float s = -2.0f;
        if (j >= 0 && j != r)
            s = dir ? thread_dot(x, j, r) : thread_dot(x, r, j);
        best = fmaxf(best, s);
        __syncwarp();
    };

    // ---- pass 2: reload (L1-hit), compare, stream groups ----
#pragma unroll
    for (int c = 0; c < 4; c++) {
        uint4 ch = *reinterpret_cast<const uint4*>(base + c * 512 + lane * 16);
        unsigned u[4] = {ch.x, ch.y, ch.z, ch.w};
        unsigned m8 = 0;
#pragma unroll
        for (int k = 0; k < 4; k++) {
            __nv_bfloat162 b2 = *reinterpret_cast<__nv_bfloat162*>(&u[k]);
            if (__low2float(b2)  >= thr) m8 |= 1u << (2 * k);
            if (__high2float(b2) >= thr) m8 |= 1u << (2 * k + 1);
        }
        unsigned bal = __ballot_sync(~0u, m8 != 0);
        while (bal) {
            int src = __ffs(bal) - 1; bal &= bal - 1;
            unsigned mm = __shfl_sync(~0u, m8, src);
            while (mm) {
                int bit = __ffs(mm) - 1; mm &= mm - 1;
                int j0 = (c * 256 + src * 8 + bit) * 8;
                __syncwarp();
                if (lane < 8) lst[warp][cnt + lane] = j0 + lane;
                cnt += 8;
                if (cnt >= 32) {
                    drain(32);
                    int rem = cnt - 32;
                    int tmp = (lane < rem) ? lst[warp][32 + lane] : 0;
                    __syncwarp();
                    if (lane < rem) lst[warp][lane] = tmp;
                    cnt = rem;
                }
            }
        }
    }
    if (cnt > 0) drain(cnt);

#pragma unroll
    for (int st = 16; st; st >>= 1) best = fmaxf(best, __shfl_xor_sync(~0u, best, st));

    if (dir == 0) {
        float d = exact_dot(x, r, r, lane);
        if (lane == 0) { g_erow[r] = best; g_diag[r] = d; }
    } else if (lane == 0) {
        g_ecol[r] = best;
    }
}

__global__ void finish_kernel() {
    __shared__ float red[256];
    int i = blockIdx.x * 256 + threadIdx.x;
    float smax = fmaxf(g_erow[i], g_ecol[i]);
    float neg = sqrtf((1.0f - smax + EPSV) * 2.0f);
    float pos = sqrtf((1.0f - g_diag[i] + EPSV) * 2.0f);
    float t = fmaxf(1.0f - neg + pos, 0.0f);
    red[threadIdx.x] = t;
    __syncthreads();
#pragma unroll
    for (int s = 128; s > 0; s >>= 1) {
        if (threadIdx.x < s) red[threadIdx.x] += red[threadIdx.x + s];
        __syncthreads();
    }
    if (threadIdx.x == 0) g_partial[blockIdx.x] = red[0];
}

__global__ void final_kernel(float* __restrict__ out) {
    if (threadIdx.x == 0) {
        float s = 0.0f;
        for (int i = 0; i < CNT / 256; i++) s += g_partial[i];
        out[0] = s / (float)CNT;
    }
}

extern "C" void kernel_launch(void* const* d_in, const int* in_sizes, int n_in,
                              void* d_out, int out_size) {
    (void)in_sizes; (void)n_in; (void)out_size;
    const float* x = (const float*)d_in[0];
    float* out = (float*)d_out;

    cudaFuncSetAttribute((const void*)gemm_screen,
                         cudaFuncAttributeMaxDynamicSharedMemorySize, SM_TOTAL);

    maxabs_kernel<<<1024, 256>>>(x);
    quant_kernel<<<2 * CNT * KDIM / 4 / 256, 256>>>(x);
    dim3 grid(CNT / 128, CNT / 128);
    gemm_screen<<<grid, 256, SM_TOTAL>>>();
    dim3 sgrid(CNT / 8, 2);
    scan6<<<sgrid, 256>>>(x);
    finish_kernel<<<CNT / 256, 256>>>();
    final_kernel<<<1, 32>>>(out);
}